// round 11
// baseline (speedup 1.0000x reference)
#include <cuda_runtime.h>
#include <cuda_fp16.h>
#include <cstdint>

#define OUT_DIM 4096
#define IN_DIM  4096
#define M_DIM   8192
#define CB_BLK  8

// ---- GEMM tiling ----
#define BM 128
#define BN 256
#define BK 128
#define NCHUNK (IN_DIM / BK)      // 32
#define NTHREADS 512
#define PITCHB 272                // bytes per smem row (256 data + 16 pad)
#define ATILE  (128 * PITCHB)     // 34816
#define BTILE  (256 * PITCHB)     // 69632
#define SA_OFF 0
#define SB_OFF (ATILE)
#define STAGEB (ATILE + BTILE)    // 104448
#define NSTAGE 2
#define SMEM_TOTAL (NSTAGE * STAGEB)   // 208896 (204 KB)

// fp16 copies (static device scratch; allocation-guard safe)
__device__ __align__(16) __half g_Wf[(size_t)OUT_DIM * IN_DIM];
__device__ __align__(16) __half g_xf[(size_t)M_DIM * IN_DIM];

// ---------------------------------------------------------------------------
// helpers
// ---------------------------------------------------------------------------
__device__ __forceinline__ uint32_t smem_u32(const void* p) {
    uint32_t a;
    asm("{ .reg .u64 t; cvta.to.shared.u64 t, %1; cvt.u32.u64 %0, t; }" : "=r"(a) : "l"(p));
    return a;
}
__device__ __forceinline__ void cp16(uint32_t saddr, const void* gaddr) {
    asm volatile("cp.async.cg.shared.global [%0], [%1], 16;" :: "r"(saddr), "l"(gaddr));
}
__device__ __forceinline__ void cp_commit() {
    asm volatile("cp.async.commit_group;" ::: "memory");
}
__device__ __forceinline__ void cp_wait0() {
    asm volatile("cp.async.wait_group 0;" ::: "memory");
}
__device__ __forceinline__ void ldm_x4(uint32_t* r, uint32_t addr) {
    asm volatile("ldmatrix.sync.aligned.m8n8.x4.shared.b16 {%0,%1,%2,%3}, [%4];"
                 : "=r"(r[0]), "=r"(r[1]), "=r"(r[2]), "=r"(r[3]) : "r"(addr));
}
__device__ __forceinline__ void mma16816(float* c, const uint32_t* a, const uint32_t* b) {
    asm volatile(
        "mma.sync.aligned.m16n8k16.row.col.f32.f16.f16.f32 "
        "{%0,%1,%2,%3}, {%4,%5,%6,%7}, {%8,%9}, {%0,%1,%2,%3};"
        : "+f"(c[0]), "+f"(c[1]), "+f"(c[2]), "+f"(c[3])
        : "r"(a[0]), "r"(a[1]), "r"(a[2]), "r"(a[3]), "r"(b[0]), "r"(b[1]));
}

// ---------------------------------------------------------------------------
// Prep 1: VQ decompress + fold scale -> fp16 W
// ---------------------------------------------------------------------------
__global__ void __launch_bounds__(256) decompress_kernel(
    const int* __restrict__ labels,
    const float* __restrict__ centroids,
    const float* __restrict__ scale)
{
    int j = blockIdx.x * blockDim.x + threadIdx.x;   // 0 .. 2097151
    int lab = labels[j] & 0xFF;
    const float4* c = reinterpret_cast<const float4*>(centroids + (size_t)lab * CB_BLK);
    float4 c0 = c[0], c1 = c[1];
    int k = (j * CB_BLK) & (IN_DIM - 1);
    const float4* s = reinterpret_cast<const float4*>(scale + k);
    float4 s0 = s[0], s1 = s[1];
    float w[8] = { c0.x * s0.x, c0.y * s0.y, c0.z * s0.z, c0.w * s0.w,
                   c1.x * s1.x, c1.y * s1.y, c1.z * s1.z, c1.w * s1.w };
    __align__(16) __half h[8];
    #pragma unroll
    for (int t = 0; t < 8; t++) h[t] = __float2half_rn(w[t]);
    *reinterpret_cast<uint4*>(&g_Wf[(size_t)j * CB_BLK]) = *reinterpret_cast<uint4*>(h);
}

// ---------------------------------------------------------------------------
// Prep 2: x -> fp16
// ---------------------------------------------------------------------------
__global__ void __launch_bounds__(256) cvt_x_kernel(const float* __restrict__ x)
{
    size_t i = (size_t)blockIdx.x * blockDim.x + threadIdx.x;   // float4 index
    float4 v = reinterpret_cast<const float4*>(x)[i];
    __align__(8) __half h[4];
    h[0] = __float2half_rn(v.x); h[1] = __float2half_rn(v.y);
    h[2] = __float2half_rn(v.z); h[3] = __float2half_rn(v.w);
    *reinterpret_cast<uint2*>(&g_xf[i * 4]) = *reinterpret_cast<uint2*>(h);
}

// ---------------------------------------------------------------------------
// Single-pass fp16 GEMM (fp32 accum): C = xf @ Wf^T + bias
// 128x256 CTA tile, BK=128, 2-stage cp.async pipeline, 16 warps of 64x32.
// Register fragment double-buffering: prefetch k-step s16+1 fragments while
// computing s16's MMAs -> hides LDSM latency inside the chunk.
// ---------------------------------------------------------------------------
__global__ void __launch_bounds__(NTHREADS, 1) gemm_mma_kernel(
    const float* __restrict__ bias,
    float* __restrict__ C)
{
    extern __shared__ char smem[];
    const uint32_t sb = smem_u32(smem);
    const int tid  = threadIdx.x;
    const int wid  = tid >> 5;
    const int lane = tid & 31;
    const int bm = blockIdx.y * BM;
    const int bn = blockIdx.x * BN;
    const int warp_m = (wid >> 3) * 64;     // 0 or 64
    const int warp_n = (wid & 7) * 32;      // 0,32,...,224

    float acc[4][4][4];
    #pragma unroll
    for (int m = 0; m < 4; m++)
        #pragma unroll
        for (int n = 0; n < 4; n++)
            #pragma unroll
            for (int v = 0; v < 4; v++) acc[m][n][v] = 0.0f;

    // one stage: A 128 rows + B 256 rows, 256B/row; 12 cp16 per thread
    auto issue = [&](int ch, int stg) {
        const int k0 = ch * BK;
        const uint32_t sbase = sb + stg * STAGEB;
        #pragma unroll
        for (int i = 0; i < 4; i++) {
            const int u = tid + i * NTHREADS;
            const int r = u >> 4;              // 0..127
            const int c = u & 15;              // 16B segment 0..15
            const uint32_t so = (uint32_t)(r * PITCHB + c * 16);
            cp16(sbase + SA_OFF + so, g_xf + (size_t)(bm + r) * IN_DIM + k0 + c * 8);
        }
        #pragma unroll
        for (int i = 0; i < 8; i++) {
            const int u = tid + i * NTHREADS;
            const int r = u >> 4;              // 0..255
            const int c = u & 15;
            const uint32_t so = (uint32_t)(r * PITCHB + c * 16);
            cp16(sbase + SB_OFF + so, g_Wf + (size_t)(bn + r) * IN_DIM + k0 + c * 8);
        }
    };

    issue(0, 0);
    cp_commit();

    // ldmatrix lane addressing (byte offsets within a tile)
    const uint32_t a_lane_off =
        (uint32_t)((warp_m + (lane & 15)) * PITCHB + (lane >> 4) * 16);
    const int b_n0 = warp_n + (lane & 7) + ((lane >> 4) << 3);
    const uint32_t b_lane_off =
        (uint32_t)(b_n0 * PITCHB + ((lane >> 3) & 1) * 16);

    // double-buffered fragments
    uint32_t ah[2][4][4];
    uint32_t th[2][2][4];

    for (int ch = 0; ch < NCHUNK; ch++) {
        cp_wait0();
        __syncthreads();            // single barrier per chunk
        if (ch + 1 < NCHUNK) issue(ch + 1, (ch + 1) & 1);
        cp_commit();

        const uint32_t sbase = sb + (ch & 1) * STAGEB;

        // prologue: load fragments for s16 = 0 into buffer 0
        #pragma unroll
        for (int m = 0; m < 4; m++)
            ldm_x4(ah[0][m], sbase + SA_OFF + a_lane_off + (uint32_t)(m * 16 * PITCHB));
        #pragma unroll
        for (int np = 0; np < 2; np++)
            ldm_x4(th[0][np], sbase + SB_OFF + b_lane_off + (uint32_t)(np * 16 * PITCHB));

        #pragma unroll
        for (int s16 = 0; s16 < 8; s16++) {
            const int cur = s16 & 1;
            const int nxt = cur ^ 1;
            if (s16 < 7) {
                const uint32_t kb = (uint32_t)((s16 + 1) * 32);   // next k-step
                #pragma unroll
                for (int m = 0; m < 4; m++)
                    ldm_x4(ah[nxt][m],
                           sbase + SA_OFF + a_lane_off + (uint32_t)(m * 16 * PITCHB) + kb);
                #pragma unroll
                for (int np = 0; np < 2; np++)
                    ldm_x4(th[nxt][np],
                           sbase + SB_OFF + b_lane_off + (uint32_t)(np * 16 * PITCHB) + kb);
            }
            #pragma unroll
            for (int np = 0; np < 2; np++)
                #pragma unroll
                for (int m = 0; m < 4; m++) {
                    mma16816(acc[m][np * 2],     ah[cur][m], th[cur][np]);
                    mma16816(acc[m][np * 2 + 1], ah[cur][m], th[cur][np] + 2);
                }
        }
    }

    // Epilogue: add bias, store fp32.
    const int erow = lane >> 2;
    const int ecol = (lane & 3) * 2;
    #pragma unroll
    for (int m = 0; m < 4; m++) {
        const size_t row = (size_t)(bm + warp_m + m * 16 + erow);
        #pragma unroll
        for (int n = 0; n < 4; n++) {
            const int col = bn + warp_n + n * 8 + ecol;
            const float bx = bias[col], by = bias[col + 1];
            float2 o0 = make_float2(acc[m][n][0] + bx, acc[m][n][1] + by);
            float2 o1 = make_float2(acc[m][n][2] + bx, acc[m][n][3] + by);
            *reinterpret_cast<float2*>(C + row * OUT_DIM + col) = o0;
            *reinterpret_cast<float2*>(C + (row + 8) * OUT_DIM + col) = o1;
        }
    }
}

// ---------------------------------------------------------------------------
// Launch
// ---------------------------------------------------------------------------
extern "C" void kernel_launch(void* const* d_in, const int* in_sizes, int n_in,
                              void* d_out, int out_size)
{
    const float* x         = (const float*)d_in[0];      // [4,2048,4096]
    const float* centroids = (const float*)d_in[1];      // [256,8]
    const int*   labels    = (const int*)d_in[2];        // [2097152] int32
    const float* scale     = (const float*)d_in[3];      // [4096]
    const float* bias      = (const float*)d_in[4];      // [4096]
    float*       out       = (float*)d_out;              // [8192,4096]

    (void)in_sizes; (void)n_in; (void)out_size;

    cudaFuncSetAttribute(gemm_mma_kernel,
                         cudaFuncAttributeMaxDynamicSharedMemorySize, SMEM_TOTAL);

    decompress_kernel<<<(OUT_DIM * IN_DIM / CB_BLK) / 256, 256>>>(labels, centroids, scale);
    cvt_x_kernel<<<(int)(((size_t)M_DIM * IN_DIM / 4) / 256), 256>>>(x);

    dim3 grid(OUT_DIM / BN, M_DIM / BM);   // (16, 64)
    gemm_mma_kernel<<<grid, NTHREADS, SMEM_TOTAL>>>(bias, out);
}

// round 12
// speedup vs baseline: 1.1993x; 1.1993x over previous
#include <cuda_runtime.h>
#include <cuda_fp16.h>
#include <cstdint>

#define OUT_DIM 4096
#define IN_DIM  4096
#define M_DIM   8192
#define CB_BLK  8

// ---- GEMM tiling ----
#define BM 128
#define BN 256
#define BK 128
#define NCHUNK (IN_DIM / BK)      // 32
#define NTHREADS 512
#define PITCHB 272                // bytes per smem row (256 data + 16 pad)
#define ATILE  (128 * PITCHB)     // 34816
#define BTILE  (256 * PITCHB)     // 69632
#define SA_OFF 0
#define SB_OFF (ATILE)
#define STAGEB (ATILE + BTILE)    // 104448
#define NSTAGE 2
#define SMEM_TOTAL (NSTAGE * STAGEB)   // 208896 (204 KB)

// fp16 copies (static device scratch; allocation-guard safe)
__device__ __align__(16) __half g_Wf[(size_t)OUT_DIM * IN_DIM];
__device__ __align__(16) __half g_xf[(size_t)M_DIM * IN_DIM];

// ---------------------------------------------------------------------------
// helpers
// ---------------------------------------------------------------------------
__device__ __forceinline__ uint32_t smem_u32(const void* p) {
    uint32_t a;
    asm("{ .reg .u64 t; cvta.to.shared.u64 t, %1; cvt.u32.u64 %0, t; }" : "=r"(a) : "l"(p));
    return a;
}
__device__ __forceinline__ void cp16(uint32_t saddr, const void* gaddr) {
    asm volatile("cp.async.cg.shared.global [%0], [%1], 16;" :: "r"(saddr), "l"(gaddr));
}
__device__ __forceinline__ void cp_commit() {
    asm volatile("cp.async.commit_group;" ::: "memory");
}
__device__ __forceinline__ void cp_wait0() {
    asm volatile("cp.async.wait_group 0;" ::: "memory");
}
__device__ __forceinline__ void ldm_x4(uint32_t* r, uint32_t addr) {
    asm volatile("ldmatrix.sync.aligned.m8n8.x4.shared.b16 {%0,%1,%2,%3}, [%4];"
                 : "=r"(r[0]), "=r"(r[1]), "=r"(r[2]), "=r"(r[3]) : "r"(addr));
}
__device__ __forceinline__ void mma16816(float* c, const uint32_t* a, const uint32_t* b) {
    asm volatile(
        "mma.sync.aligned.m16n8k16.row.col.f32.f16.f16.f32 "
        "{%0,%1,%2,%3}, {%4,%5,%6,%7}, {%8,%9}, {%0,%1,%2,%3};"
        : "+f"(c[0]), "+f"(c[1]), "+f"(c[2]), "+f"(c[3])
        : "r"(a[0]), "r"(a[1]), "r"(a[2]), "r"(a[3]), "r"(b[0]), "r"(b[1]));
}

// ---------------------------------------------------------------------------
// Prep 1: VQ decompress + fold scale -> fp16 W
// ---------------------------------------------------------------------------
__global__ void __launch_bounds__(256) decompress_kernel(
    const int* __restrict__ labels,
    const float* __restrict__ centroids,
    const float* __restrict__ scale)
{
    int j = blockIdx.x * blockDim.x + threadIdx.x;   // 0 .. 2097151
    int lab = labels[j] & 0xFF;
    const float4* c = reinterpret_cast<const float4*>(centroids + (size_t)lab * CB_BLK);
    float4 c0 = c[0], c1 = c[1];
    int k = (j * CB_BLK) & (IN_DIM - 1);
    const float4* s = reinterpret_cast<const float4*>(scale + k);
    float4 s0 = s[0], s1 = s[1];
    float w[8] = { c0.x * s0.x, c0.y * s0.y, c0.z * s0.z, c0.w * s0.w,
                   c1.x * s1.x, c1.y * s1.y, c1.z * s1.z, c1.w * s1.w };
    __align__(16) __half h[8];
    #pragma unroll
    for (int t = 0; t < 8; t++) h[t] = __float2half_rn(w[t]);
    *reinterpret_cast<uint4*>(&g_Wf[(size_t)j * CB_BLK]) = *reinterpret_cast<uint4*>(h);
}

// ---------------------------------------------------------------------------
// Prep 2: x -> fp16
// ---------------------------------------------------------------------------
__global__ void __launch_bounds__(256) cvt_x_kernel(const float* __restrict__ x)
{
    size_t i = (size_t)blockIdx.x * blockDim.x + threadIdx.x;   // float4 index
    float4 v = reinterpret_cast<const float4*>(x)[i];
    __align__(8) __half h[4];
    h[0] = __float2half_rn(v.x); h[1] = __float2half_rn(v.y);
    h[2] = __float2half_rn(v.z); h[3] = __float2half_rn(v.w);
    *reinterpret_cast<uint2*>(&g_xf[i * 4]) = *reinterpret_cast<uint2*>(h);
}

// ---------------------------------------------------------------------------
// Single-pass fp16 GEMM (fp32 accum): C = xf @ Wf^T + bias
// 128x256 CTA tile, BK=128, 2-stage cp.async pipeline, one barrier per chunk,
// 16 warps of 64x32. Next-chunk cp.async issue is SPREAD across the k-steps
// (4 parts after s16 = 0,2,4,6) to avoid the chunk-head smem-crossbar burst.
// ---------------------------------------------------------------------------
__global__ void __launch_bounds__(NTHREADS, 1) gemm_mma_kernel(
    const float* __restrict__ bias,
    float* __restrict__ C)
{
    extern __shared__ char smem[];
    const uint32_t sb = smem_u32(smem);
    const int tid  = threadIdx.x;
    const int wid  = tid >> 5;
    const int lane = tid & 31;
    const int bm = blockIdx.y * BM;
    const int bn = blockIdx.x * BN;
    const int warp_m = (wid >> 3) * 64;     // 0 or 64
    const int warp_n = (wid & 7) * 32;      // 0,32,...,224

    float acc[4][4][4];
    #pragma unroll
    for (int m = 0; m < 4; m++)
        #pragma unroll
        for (int n = 0; n < 4; n++)
            #pragma unroll
            for (int v = 0; v < 4; v++) acc[m][n][v] = 0.0f;

    // One quarter of a stage's loads: part p covers A seg p and B segs 2p, 2p+1.
    auto issue_part = [&](int ch, int stg, int p) {
        const int k0 = ch * BK;
        const uint32_t sbase = sb + stg * STAGEB;
        {
            const int u = tid + p * NTHREADS;
            const int r = u >> 4;              // 0..127
            const int c = u & 15;              // 16B segment
            const uint32_t so = (uint32_t)(r * PITCHB + c * 16);
            cp16(sbase + SA_OFF + so, g_xf + (size_t)(bm + r) * IN_DIM + k0 + c * 8);
        }
        #pragma unroll
        for (int i = 0; i < 2; i++) {
            const int u = tid + (p * 2 + i) * NTHREADS;
            const int r = u >> 4;              // 0..255
            const int c = u & 15;
            const uint32_t so = (uint32_t)(r * PITCHB + c * 16);
            cp16(sbase + SB_OFF + so, g_Wf + (size_t)(bn + r) * IN_DIM + k0 + c * 8);
        }
    };

    #pragma unroll
    for (int p = 0; p < 4; p++) issue_part(0, 0, p);
    cp_commit();

    // ldmatrix lane addressing (byte offsets within a tile)
    const uint32_t a_lane_off =
        (uint32_t)((warp_m + (lane & 15)) * PITCHB + (lane >> 4) * 16);
    const int b_n0 = warp_n + (lane & 7) + ((lane >> 4) << 3);
    const uint32_t b_lane_off =
        (uint32_t)(b_n0 * PITCHB + ((lane >> 3) & 1) * 16);

    for (int ch = 0; ch < NCHUNK; ch++) {
        cp_wait0();
        __syncthreads();            // single barrier per chunk
        const bool more = (ch + 1 < NCHUNK);
        const int  nstg = (ch + 1) & 1;

        const uint32_t sbase = sb + (ch & 1) * STAGEB;
        #pragma unroll
        for (int s16 = 0; s16 < 8; s16++) {
            const uint32_t kb = (uint32_t)(s16 * 32);   // 16 fp16 = 32B
            uint32_t ah[4][4];
            #pragma unroll
            for (int m = 0; m < 4; m++) {
                const uint32_t off = a_lane_off + (uint32_t)(m * 16 * PITCHB) + kb;
                ldm_x4(ah[m], sbase + SA_OFF + off);
            }
            #pragma unroll
            for (int np = 0; np < 2; np++) {            // 2 x 16-col B blocks
                const uint32_t off = b_lane_off + (uint32_t)(np * 16 * PITCHB) + kb;
                uint32_t th[4];
                ldm_x4(th, sbase + SB_OFF + off);
                #pragma unroll
                for (int m = 0; m < 4; m++) {
                    mma16816(acc[m][np * 2],     ah[m], th);
                    mma16816(acc[m][np * 2 + 1], ah[m], th + 2);
                }
            }
            // trickle next-chunk loads after k-steps 0,2,4,6
            if (more && (s16 & 1) == 0) issue_part(ch + 1, nstg, s16 >> 1);
        }
        if (more) cp_commit();
    }

    // Epilogue: add bias, store fp32.
    const int erow = lane >> 2;
    const int ecol = (lane & 3) * 2;
    #pragma unroll
    for (int m = 0; m < 4; m++) {
        const size_t row = (size_t)(bm + warp_m + m * 16 + erow);
        #pragma unroll
        for (int n = 0; n < 4; n++) {
            const int col = bn + warp_n + n * 8 + ecol;
            const float bx = bias[col], by = bias[col + 1];
            float2 o0 = make_float2(acc[m][n][0] + bx, acc[m][n][1] + by);
            float2 o1 = make_float2(acc[m][n][2] + bx, acc[m][n][3] + by);
            *reinterpret_cast<float2*>(C + row * OUT_DIM + col) = o0;
            *reinterpret_cast<float2*>(C + (row + 8) * OUT_DIM + col) = o1;
        }
    }
}

// ---------------------------------------------------------------------------
// Launch
// ---------------------------------------------------------------------------
extern "C" void kernel_launch(void* const* d_in, const int* in_sizes, int n_in,
                              void* d_out, int out_size)
{
    const float* x         = (const float*)d_in[0];      // [4,2048,4096]
    const float* centroids = (const float*)d_in[1];      // [256,8]
    const int*   labels    = (const int*)d_in[2];        // [2097152] int32
    const float* scale     = (const float*)d_in[3];      // [4096]
    const float* bias      = (const float*)d_in[4];      // [4096]
    float*       out       = (float*)d_out;              // [8192,4096]

    (void)in_sizes; (void)n_in; (void)out_size;

    cudaFuncSetAttribute(gemm_mma_kernel,
                         cudaFuncAttributeMaxDynamicSharedMemorySize, SMEM_TOTAL);

    decompress_kernel<<<(OUT_DIM * IN_DIM / CB_BLK) / 256, 256>>>(labels, centroids, scale);
    cvt_x_kernel<<<(int)(((size_t)M_DIM * IN_DIM / 4) / 256), 256>>>(x);

    dim3 grid(OUT_DIM / BN, M_DIM / BM);   // (16, 64)
    gemm_mma_kernel<<<grid, NTHREADS, SMEM_TOTAL>>>(bias, out);
}

// round 13
// speedup vs baseline: 1.2580x; 1.0489x over previous
#include <cuda_runtime.h>
#include <cuda_fp16.h>
#include <cstdint>

#define OUT_DIM 4096
#define IN_DIM  4096
#define M_DIM   8192
#define CB_BLK  8

// ---- GEMM tiling ----
#define BM 128
#define BN 256
#define BK 128
#define NCHUNK (IN_DIM / BK)      // 32
#define NTHREADS 512
#define PITCHB 272                // bytes per smem row (256 data + 16 pad)
#define ATILE  (128 * PITCHB)     // 34816
#define BTILE  (256 * PITCHB)     // 69632
#define SA_OFF 0
#define SB_OFF (ATILE)
#define STAGEB (ATILE + BTILE)    // 104448
#define NSTAGE 2
#define SMEM_TOTAL (NSTAGE * STAGEB)   // 208896 (204 KB)

// fp16 copies (static device scratch; allocation-guard safe)
__device__ __align__(16) __half g_Wf[(size_t)OUT_DIM * IN_DIM];
__device__ __align__(16) __half g_xf[(size_t)M_DIM * IN_DIM];

// ---------------------------------------------------------------------------
// helpers
// ---------------------------------------------------------------------------
__device__ __forceinline__ uint32_t smem_u32(const void* p) {
    uint32_t a;
    asm("{ .reg .u64 t; cvta.to.shared.u64 t, %1; cvt.u32.u64 %0, t; }" : "=r"(a) : "l"(p));
    return a;
}
__device__ __forceinline__ void cp16(uint32_t saddr, const void* gaddr) {
    asm volatile("cp.async.cg.shared.global [%0], [%1], 16;" :: "r"(saddr), "l"(gaddr));
}
__device__ __forceinline__ void cp_commit() {
    asm volatile("cp.async.commit_group;" ::: "memory");
}
__device__ __forceinline__ void cp_wait0() {
    asm volatile("cp.async.wait_group 0;" ::: "memory");
}
__device__ __forceinline__ void ldm_x4(uint32_t* r, uint32_t addr) {
    asm volatile("ldmatrix.sync.aligned.m8n8.x4.shared.b16 {%0,%1,%2,%3}, [%4];"
                 : "=r"(r[0]), "=r"(r[1]), "=r"(r[2]), "=r"(r[3]) : "r"(addr));
}
__device__ __forceinline__ void mma16816(float* c, const uint32_t* a, const uint32_t* b) {
    asm volatile(
        "mma.sync.aligned.m16n8k16.row.col.f32.f16.f16.f32 "
        "{%0,%1,%2,%3}, {%4,%5,%6,%7}, {%8,%9}, {%0,%1,%2,%3};"
        : "+f"(c[0]), "+f"(c[1]), "+f"(c[2]), "+f"(c[3])
        : "r"(a[0]), "r"(a[1]), "r"(a[2]), "r"(a[3]), "r"(b[0]), "r"(b[1]));
}

// ---------------------------------------------------------------------------
// Prep 1: VQ decompress + fold scale -> fp16 W
// ---------------------------------------------------------------------------
__global__ void __launch_bounds__(256) decompress_kernel(
    const int* __restrict__ labels,
    const float* __restrict__ centroids,
    const float* __restrict__ scale)
{
    int j = blockIdx.x * blockDim.x + threadIdx.x;   // 0 .. 2097151
    int lab = labels[j] & 0xFF;
    const float4* c = reinterpret_cast<const float4*>(centroids + (size_t)lab * CB_BLK);
    float4 c0 = c[0], c1 = c[1];
    int k = (j * CB_BLK) & (IN_DIM - 1);
    const float4* s = reinterpret_cast<const float4*>(scale + k);
    float4 s0 = s[0], s1 = s[1];
    float w[8] = { c0.x * s0.x, c0.y * s0.y, c0.z * s0.z, c0.w * s0.w,
                   c1.x * s1.x, c1.y * s1.y, c1.z * s1.z, c1.w * s1.w };
    __align__(16) __half h[8];
    #pragma unroll
    for (int t = 0; t < 8; t++) h[t] = __float2half_rn(w[t]);
    *reinterpret_cast<uint4*>(&g_Wf[(size_t)j * CB_BLK]) = *reinterpret_cast<uint4*>(h);
}

// ---------------------------------------------------------------------------
// Prep 2: x -> fp16
// ---------------------------------------------------------------------------
__global__ void __launch_bounds__(256) cvt_x_kernel(const float* __restrict__ x)
{
    size_t i = (size_t)blockIdx.x * blockDim.x + threadIdx.x;   // float4 index
    float4 v = reinterpret_cast<const float4*>(x)[i];
    __align__(8) __half h[4];
    h[0] = __float2half_rn(v.x); h[1] = __float2half_rn(v.y);
    h[2] = __float2half_rn(v.z); h[3] = __float2half_rn(v.w);
    *reinterpret_cast<uint2*>(&g_xf[i * 4]) = *reinterpret_cast<uint2*>(h);
}

// ---------------------------------------------------------------------------
// Single-pass fp16 GEMM (fp32 accum): C = xf @ Wf^T + bias
// 128x256 CTA tile, BK=128, 2-stage cp.async pipeline, one barrier per chunk,
// 16 warps of 64x32. Next-chunk cp.async issue spread over the FIRST FOUR
// k-steps (s16 = 0..3): avoids the chunk-head crossbar burst while giving the
// last-issued part >= 4 k-steps of compute cover before the next cp_wait0.
// ---------------------------------------------------------------------------
__global__ void __launch_bounds__(NTHREADS, 1) gemm_mma_kernel(
    const float* __restrict__ bias,
    float* __restrict__ C)
{
    extern __shared__ char smem[];
    const uint32_t sb = smem_u32(smem);
    const int tid  = threadIdx.x;
    const int wid  = tid >> 5;
    const int lane = tid & 31;
    const int bm = blockIdx.y * BM;
    const int bn = blockIdx.x * BN;
    const int warp_m = (wid >> 3) * 64;     // 0 or 64
    const int warp_n = (wid & 7) * 32;      // 0,32,...,224

    float acc[4][4][4];
    #pragma unroll
    for (int m = 0; m < 4; m++)
        #pragma unroll
        for (int n = 0; n < 4; n++)
            #pragma unroll
            for (int v = 0; v < 4; v++) acc[m][n][v] = 0.0f;

    // One quarter of a stage's loads: part p covers A seg p and B segs 2p, 2p+1.
    auto issue_part = [&](int ch, int stg, int p) {
        const int k0 = ch * BK;
        const uint32_t sbase = sb + stg * STAGEB;
        {
            const int u = tid + p * NTHREADS;
            const int r = u >> 4;              // 0..127
            const int c = u & 15;              // 16B segment
            const uint32_t so = (uint32_t)(r * PITCHB + c * 16);
            cp16(sbase + SA_OFF + so, g_xf + (size_t)(bm + r) * IN_DIM + k0 + c * 8);
        }
        #pragma unroll
        for (int i = 0; i < 2; i++) {
            const int u = tid + (p * 2 + i) * NTHREADS;
            const int r = u >> 4;              // 0..255
            const int c = u & 15;
            const uint32_t so = (uint32_t)(r * PITCHB + c * 16);
            cp16(sbase + SB_OFF + so, g_Wf + (size_t)(bn + r) * IN_DIM + k0 + c * 8);
        }
    };

    #pragma unroll
    for (int p = 0; p < 4; p++) issue_part(0, 0, p);
    cp_commit();

    // ldmatrix lane addressing (byte offsets within a tile)
    const uint32_t a_lane_off =
        (uint32_t)((warp_m + (lane & 15)) * PITCHB + (lane >> 4) * 16);
    const int b_n0 = warp_n + (lane & 7) + ((lane >> 4) << 3);
    const uint32_t b_lane_off =
        (uint32_t)(b_n0 * PITCHB + ((lane >> 3) & 1) * 16);

    for (int ch = 0; ch < NCHUNK; ch++) {
        cp_wait0();
        __syncthreads();            // single barrier per chunk
        const bool more = (ch + 1 < NCHUNK);
        const int  nstg = (ch + 1) & 1;

        const uint32_t sbase = sb + (ch & 1) * STAGEB;
        #pragma unroll
        for (int s16 = 0; s16 < 8; s16++) {
            const uint32_t kb = (uint32_t)(s16 * 32);   // 16 fp16 = 32B
            uint32_t ah[4][4];
            #pragma unroll
            for (int m = 0; m < 4; m++) {
                const uint32_t off = a_lane_off + (uint32_t)(m * 16 * PITCHB) + kb;
                ldm_x4(ah[m], sbase + SA_OFF + off);
            }
            #pragma unroll
            for (int np = 0; np < 2; np++) {            // 2 x 16-col B blocks
                const uint32_t off = b_lane_off + (uint32_t)(np * 16 * PITCHB) + kb;
                uint32_t th[4];
                ldm_x4(th, sbase + SB_OFF + off);
                #pragma unroll
                for (int m = 0; m < 4; m++) {
                    mma16816(acc[m][np * 2],     ah[m], th);
                    mma16816(acc[m][np * 2 + 1], ah[m], th + 2);
                }
            }
            // trickle next-chunk loads after k-steps 0..3; commit after the last
            if (more && s16 < 4) {
                issue_part(ch + 1, nstg, s16);
                if (s16 == 3) cp_commit();
            }
        }
    }

    // Epilogue: add bias, store fp32.
    const int erow = lane >> 2;
    const int ecol = (lane & 3) * 2;
    #pragma unroll
    for (int m = 0; m < 4; m++) {
        const size_t row = (size_t)(bm + warp_m + m * 16 + erow);
        #pragma unroll
        for (int n = 0; n < 4; n++) {
            const int col = bn + warp_n + n * 8 + ecol;
            const float bx = bias[col], by = bias[col + 1];
            float2 o0 = make_float2(acc[m][n][0] + bx, acc[m][n][1] + by);
            float2 o1 = make_float2(acc[m][n][2] + bx, acc[m][n][3] + by);
            *reinterpret_cast<float2*>(C + row * OUT_DIM + col) = o0;
            *reinterpret_cast<float2*>(C + (row + 8) * OUT_DIM + col) = o1;
        }
    }
}

// ---------------------------------------------------------------------------
// Launch
// ---------------------------------------------------------------------------
extern "C" void kernel_launch(void* const* d_in, const int* in_sizes, int n_in,
                              void* d_out, int out_size)
{
    const float* x         = (const float*)d_in[0];      // [4,2048,4096]
    const float* centroids = (const float*)d_in[1];      // [256,8]
    const int*   labels    = (const int*)d_in[2];        // [2097152] int32
    const float* scale     = (const float*)d_in[3];      // [4096]
    const float* bias      = (const float*)d_in[4];      // [4096]
    float*       out       = (float*)d_out;              // [8192,4096]

    (void)in_sizes; (void)n_in; (void)out_size;

    cudaFuncSetAttribute(gemm_mma_kernel,
                         cudaFuncAttributeMaxDynamicSharedMemorySize, SMEM_TOTAL);

    decompress_kernel<<<(OUT_DIM * IN_DIM / CB_BLK) / 256, 256>>>(labels, centroids, scale);
    cvt_x_kernel<<<(int)(((size_t)M_DIM * IN_DIM / 4) / 256), 256>>>(x);

    dim3 grid(OUT_DIM / BN, M_DIM / BM);   // (16, 64)
    gemm_mma_kernel<<<grid, NTHREADS, SMEM_TOTAL>>>(bias, out);
}

// round 14
// speedup vs baseline: 1.2936x; 1.0283x over previous
#include <cuda_runtime.h>
#include <cuda_fp16.h>
#include <cstdint>

#define OUT_DIM 4096
#define IN_DIM  4096
#define M_DIM   8192
#define CB_BLK  8

// ---- GEMM tiling ----
#define BM 128
#define BN 256
#define BK 128
#define NCHUNK (IN_DIM / BK)      // 32
#define NTHREADS 512
#define NCTAS 148                 // persistent: one CTA per SM
#define NTILES ((M_DIM / BM) * (OUT_DIM / BN))   // 64 * 16 = 1024
#define PITCHB 272                // bytes per smem row (256 data + 16 pad)
#define ATILE  (128 * PITCHB)     // 34816
#define BTILE  (256 * PITCHB)     // 69632
#define SA_OFF 0
#define SB_OFF (ATILE)
#define STAGEB (ATILE + BTILE)    // 104448
#define NSTAGE 2
#define SMEM_TOTAL (NSTAGE * STAGEB)   // 208896 (204 KB)

// fp16 copies (static device scratch; allocation-guard safe)
__device__ __align__(16) __half g_Wf[(size_t)OUT_DIM * IN_DIM];
__device__ __align__(16) __half g_xf[(size_t)M_DIM * IN_DIM];

// ---------------------------------------------------------------------------
// helpers
// ---------------------------------------------------------------------------
__device__ __forceinline__ uint32_t smem_u32(const void* p) {
    uint32_t a;
    asm("{ .reg .u64 t; cvta.to.shared.u64 t, %1; cvt.u32.u64 %0, t; }" : "=r"(a) : "l"(p));
    return a;
}
__device__ __forceinline__ void cp16(uint32_t saddr, const void* gaddr) {
    asm volatile("cp.async.cg.shared.global [%0], [%1], 16;" :: "r"(saddr), "l"(gaddr));
}
__device__ __forceinline__ void cp_commit() {
    asm volatile("cp.async.commit_group;" ::: "memory");
}
__device__ __forceinline__ void cp_wait0() {
    asm volatile("cp.async.wait_group 0;" ::: "memory");
}
__device__ __forceinline__ void ldm_x4(uint32_t* r, uint32_t addr) {
    asm volatile("ldmatrix.sync.aligned.m8n8.x4.shared.b16 {%0,%1,%2,%3}, [%4];"
                 : "=r"(r[0]), "=r"(r[1]), "=r"(r[2]), "=r"(r[3]) : "r"(addr));
}
__device__ __forceinline__ void mma16816(float* c, const uint32_t* a, const uint32_t* b) {
    asm volatile(
        "mma.sync.aligned.m16n8k16.row.col.f32.f16.f16.f32 "
        "{%0,%1,%2,%3}, {%4,%5,%6,%7}, {%8,%9}, {%0,%1,%2,%3};"
        : "+f"(c[0]), "+f"(c[1]), "+f"(c[2]), "+f"(c[3])
        : "r"(a[0]), "r"(a[1]), "r"(a[2]), "r"(a[3]), "r"(b[0]), "r"(b[1]));
}

// ---------------------------------------------------------------------------
// Prep 1: VQ decompress + fold scale -> fp16 W
// ---------------------------------------------------------------------------
__global__ void __launch_bounds__(256) decompress_kernel(
    const int* __restrict__ labels,
    const float* __restrict__ centroids,
    const float* __restrict__ scale)
{
    int j = blockIdx.x * blockDim.x + threadIdx.x;   // 0 .. 2097151
    int lab = labels[j] & 0xFF;
    const float4* c = reinterpret_cast<const float4*>(centroids + (size_t)lab * CB_BLK);
    float4 c0 = c[0], c1 = c[1];
    int k = (j * CB_BLK) & (IN_DIM - 1);
    const float4* s = reinterpret_cast<const float4*>(scale + k);
    float4 s0 = s[0], s1 = s[1];
    float w[8] = { c0.x * s0.x, c0.y * s0.y, c0.z * s0.z, c0.w * s0.w,
                   c1.x * s1.x, c1.y * s1.y, c1.z * s1.z, c1.w * s1.w };
    __align__(16) __half h[8];
    #pragma unroll
    for (int t = 0; t < 8; t++) h[t] = __float2half_rn(w[t]);
    *reinterpret_cast<uint4*>(&g_Wf[(size_t)j * CB_BLK]) = *reinterpret_cast<uint4*>(h);
}

// ---------------------------------------------------------------------------
// Prep 2: x -> fp16
// ---------------------------------------------------------------------------
__global__ void __launch_bounds__(256) cvt_x_kernel(const float* __restrict__ x)
{
    size_t i = (size_t)blockIdx.x * blockDim.x + threadIdx.x;   // float4 index
    float4 v = reinterpret_cast<const float4*>(x)[i];
    __align__(8) __half h[4];
    h[0] = __float2half_rn(v.x); h[1] = __float2half_rn(v.y);
    h[2] = __float2half_rn(v.z); h[3] = __float2half_rn(v.w);
    *reinterpret_cast<uint2*>(&g_xf[i * 4]) = *reinterpret_cast<uint2*>(h);
}

// ---------------------------------------------------------------------------
// Single-pass fp16 GEMM (fp32 accum): C = xf @ Wf^T + bias
// PERSISTENT: 148 CTAs, each loops over ~7 output tiles (tile += 148).
// Per tile: 128x256, BK=128, 2-stage cp.async, one barrier per chunk,
// 16 warps of 64x32. Trickled loads: during each chunk the NEXT chunk's
// loads (wrapping to the next tile's chunk 0 at tile end) are issued in 4
// parts after k-steps 0..3 -> epilogue and tile prologue fully overlap.
// ---------------------------------------------------------------------------
__global__ void __launch_bounds__(NTHREADS, 1) gemm_mma_kernel(
    const float* __restrict__ bias,
    float* __restrict__ C)
{
    extern __shared__ char smem[];
    const uint32_t sb = smem_u32(smem);
    const int tid  = threadIdx.x;
    const int wid  = tid >> 5;
    const int lane = tid & 31;
    const int warp_m = (wid >> 3) * 64;     // 0 or 64
    const int warp_n = (wid & 7) * 32;      // 0,32,...,224

    // One quarter of a chunk's loads: part p covers A seg p and B segs 2p,2p+1.
    auto issue_part = [&](int lbm, int lbn, int k0, int stg, int p) {
        const uint32_t sbase = sb + (uint32_t)stg * STAGEB;
        {
            const int u = tid + p * NTHREADS;
            const int r = u >> 4;              // 0..127
            const int c = u & 15;              // 16B segment
            const uint32_t so = (uint32_t)(r * PITCHB + c * 16);
            cp16(sbase + SA_OFF + so, g_xf + (size_t)(lbm + r) * IN_DIM + k0 + c * 8);
        }
        #pragma unroll
        for (int i = 0; i < 2; i++) {
            const int u = tid + (p * 2 + i) * NTHREADS;
            const int r = u >> 4;              // 0..255
            const int c = u & 15;
            const uint32_t so = (uint32_t)(r * PITCHB + c * 16);
            cp16(sbase + SB_OFF + so, g_Wf + (size_t)(lbn + r) * IN_DIM + k0 + c * 8);
        }
    };

    // ldmatrix lane addressing (byte offsets within a tile)
    const uint32_t a_lane_off =
        (uint32_t)((warp_m + (lane & 15)) * PITCHB + (lane >> 4) * 16);
    const int b_n0 = warp_n + (lane & 7) + ((lane >> 4) << 3);
    const uint32_t b_lane_off =
        (uint32_t)(b_n0 * PITCHB + ((lane >> 3) & 1) * 16);

    const int erow = lane >> 2;
    const int ecol = (lane & 3) * 2;

    // Prologue: first tile's chunk 0 into stage 0.
    {
        const int t0 = blockIdx.x;
        const int pbm = (t0 >> 4) * BM;
        const int pbn = (t0 & 15) * BN;
        #pragma unroll
        for (int p = 0; p < 4; p++) issue_part(pbm, pbn, 0, 0, p);
        cp_commit();
    }

    int stg = 0;
    for (int tile = blockIdx.x; tile < NTILES; tile += NCTAS) {
        const int bm = (tile >> 4) * BM;
        const int bn = (tile & 15) * BN;

        float acc[4][4][4];
        #pragma unroll
        for (int m = 0; m < 4; m++)
            #pragma unroll
            for (int n = 0; n < 4; n++)
                #pragma unroll
                for (int v = 0; v < 4; v++) acc[m][n][v] = 0.0f;

        for (int ch = 0; ch < NCHUNK; ch++) {
            cp_wait0();
            __syncthreads();            // single barrier per chunk

            // coordinates of the chunk to load (next chunk, wrapping to next tile)
            int  nch  = ch + 1;
            int  ntile = tile;
            bool more = true;
            if (nch == NCHUNK) {
                nch = 0;
                ntile = tile + NCTAS;
                if (ntile >= NTILES) more = false;
            }
            const int nbm = (ntile >> 4) * BM;
            const int nbn = (ntile & 15) * BN;
            const int nk0 = nch * BK;
            const int nstg = stg ^ 1;

            const uint32_t sbase = sb + (uint32_t)stg * STAGEB;
            #pragma unroll
            for (int s16 = 0; s16 < 8; s16++) {
                const uint32_t kb = (uint32_t)(s16 * 32);   // 16 fp16 = 32B
                uint32_t ah[4][4];
                #pragma unroll
                for (int m = 0; m < 4; m++) {
                    const uint32_t off = a_lane_off + (uint32_t)(m * 16 * PITCHB) + kb;
                    ldm_x4(ah[m], sbase + SA_OFF + off);
                }
                #pragma unroll
                for (int np = 0; np < 2; np++) {            // 2 x 16-col B blocks
                    const uint32_t off = b_lane_off + (uint32_t)(np * 16 * PITCHB) + kb;
                    uint32_t th[4];
                    ldm_x4(th, sbase + SB_OFF + off);
                    #pragma unroll
                    for (int m = 0; m < 4; m++) {
                        mma16816(acc[m][np * 2],     ah[m], th);
                        mma16816(acc[m][np * 2 + 1], ah[m], th + 2);
                    }
                }
                // trickle next-chunk loads after k-steps 0..3; commit after last
                if (more && s16 < 4) {
                    issue_part(nbm, nbn, nk0, nstg, s16);
                    if (s16 == 3) cp_commit();
                }
            }
            stg ^= 1;
        }

        // Epilogue (overlaps the in-flight next-tile chunk-0 loads)
        #pragma unroll
        for (int m = 0; m < 4; m++) {
            const size_t row = (size_t)(bm + warp_m + m * 16 + erow);
            #pragma unroll
            for (int n = 0; n < 4; n++) {
                const int col = bn + warp_n + n * 8 + ecol;
                const float bx = bias[col], by = bias[col + 1];
                float2 o0 = make_float2(acc[m][n][0] + bx, acc[m][n][1] + by);
                float2 o1 = make_float2(acc[m][n][2] + bx, acc[m][n][3] + by);
                *reinterpret_cast<float2*>(C + row * OUT_DIM + col) = o0;
                *reinterpret_cast<float2*>(C + (row + 8) * OUT_DIM + col) = o1;
            }
        }
    }
}

// ---------------------------------------------------------------------------
// Launch
// ---------------------------------------------------------------------------
extern "C" void kernel_launch(void* const* d_in, const int* in_sizes, int n_in,
                              void* d_out, int out_size)
{
    const float* x         = (const float*)d_in[0];      // [4,2048,4096]
    const float* centroids = (const float*)d_in[1];      // [256,8]
    const int*   labels    = (const int*)d_in[2];        // [2097152] int32
    const float* scale     = (const float*)d_in[3];      // [4096]
    const float* bias      = (const float*)d_in[4];      // [4096]
    float*       out       = (float*)d_out;              // [8192,4096]

    (void)in_sizes; (void)n_in; (void)out_size;

    cudaFuncSetAttribute(gemm_mma_kernel,
                         cudaFuncAttributeMaxDynamicSharedMemorySize, SMEM_TOTAL);

    decompress_kernel<<<(OUT_DIM * IN_DIM / CB_BLK) / 256, 256>>>(labels, centroids, scale);
    cvt_x_kernel<<<(int)(((size_t)M_DIM * IN_DIM / 4) / 256), 256>>>(x);

    gemm_mma_kernel<<<NCTAS, NTHREADS, SMEM_TOTAL>>>(bias, out);
}

// round 15
// speedup vs baseline: 1.3102x; 1.0128x over previous
#include <cuda_runtime.h>
#include <cuda_fp16.h>
#include <cstdint>

#define OUT_DIM 4096
#define IN_DIM  4096
#define M_DIM   8192
#define CB_BLK  8

// ---- GEMM tiling ----
#define BM 128
#define BN 256
#define BK 128
#define NCHUNK (IN_DIM / BK)      // 32
#define NTHREADS 512
#define NCTAS 148                 // persistent: one CTA per SM
#define NTILES ((M_DIM / BM) * (OUT_DIM / BN))   // 64 * 16 = 1024
#define PITCHB 272                // bytes per smem row (256 data + 16 pad)
#define ATILE  (128 * PITCHB)     // 34816
#define BTILE  (256 * PITCHB)     // 69632
#define SA_OFF 0
#define SB_OFF (ATILE)
#define STAGEB (ATILE + BTILE)    // 104448
#define NSTAGE 2
#define SMEM_TOTAL (NSTAGE * STAGEB)   // 208896 (204 KB)

// prep kernel partition
#define DEC_BLOCKS ((OUT_DIM * IN_DIM / CB_BLK) / 256)            // 8192
#define CVT_BLOCKS ((int)(((size_t)M_DIM * IN_DIM / 8) / 256))    // 16384
#define PREP_BLOCKS (DEC_BLOCKS + CVT_BLOCKS)

// fp16 copies (static device scratch; allocation-guard safe)
__device__ __align__(16) __half g_Wf[(size_t)OUT_DIM * IN_DIM];
__device__ __align__(16) __half g_xf[(size_t)M_DIM * IN_DIM];

// ---------------------------------------------------------------------------
// helpers
// ---------------------------------------------------------------------------
__device__ __forceinline__ uint32_t smem_u32(const void* p) {
    uint32_t a;
    asm("{ .reg .u64 t; cvta.to.shared.u64 t, %1; cvt.u32.u64 %0, t; }" : "=r"(a) : "l"(p));
    return a;
}
__device__ __forceinline__ void cp16(uint32_t saddr, const void* gaddr) {
    asm volatile("cp.async.cg.shared.global [%0], [%1], 16;" :: "r"(saddr), "l"(gaddr));
}
__device__ __forceinline__ void cp_commit() {
    asm volatile("cp.async.commit_group;" ::: "memory");
}
__device__ __forceinline__ void cp_wait0() {
    asm volatile("cp.async.wait_group 0;" ::: "memory");
}
__device__ __forceinline__ void ldm_x4(uint32_t* r, uint32_t addr) {
    asm volatile("ldmatrix.sync.aligned.m8n8.x4.shared.b16 {%0,%1,%2,%3}, [%4];"
                 : "=r"(r[0]), "=r"(r[1]), "=r"(r[2]), "=r"(r[3]) : "r"(addr));
}
__device__ __forceinline__ void mma16816(float* c, const uint32_t* a, const uint32_t* b) {
    asm volatile(
        "mma.sync.aligned.m16n8k16.row.col.f32.f16.f16.f32 "
        "{%0,%1,%2,%3}, {%4,%5,%6,%7}, {%8,%9}, {%0,%1,%2,%3};"
        : "+f"(c[0]), "+f"(c[1]), "+f"(c[2]), "+f"(c[3])
        : "r"(a[0]), "r"(a[1]), "r"(a[2]), "r"(a[3]), "r"(b[0]), "r"(b[1]));
}

// ---------------------------------------------------------------------------
// Fused prep: blocks [0, DEC_BLOCKS) do VQ decompress + scale-fold -> fp16 W;
// blocks [DEC_BLOCKS, PREP_BLOCKS) convert x -> fp16, 8 floats per thread.
// ---------------------------------------------------------------------------
__global__ void __launch_bounds__(256) prep_kernel(
    const int* __restrict__ labels,
    const float* __restrict__ centroids,
    const float* __restrict__ scale,
    const float* __restrict__ x)
{
    const int bid = blockIdx.x;
    if (bid < DEC_BLOCKS) {
        int j = bid * 256 + threadIdx.x;             // 0 .. 2097151
        int lab = labels[j] & 0xFF;
        const float4* c = reinterpret_cast<const float4*>(centroids + (size_t)lab * CB_BLK);
        float4 c0 = c[0], c1 = c[1];
        int k = (j * CB_BLK) & (IN_DIM - 1);
        const float4* s = reinterpret_cast<const float4*>(scale + k);
        float4 s0 = s[0], s1 = s[1];
        float w[8] = { c0.x * s0.x, c0.y * s0.y, c0.z * s0.z, c0.w * s0.w,
                       c1.x * s1.x, c1.y * s1.y, c1.z * s1.z, c1.w * s1.w };
        __align__(16) __half h[8];
        #pragma unroll
        for (int t = 0; t < 8; t++) h[t] = __float2half_rn(w[t]);
        *reinterpret_cast<uint4*>(&g_Wf[(size_t)j * CB_BLK]) = *reinterpret_cast<uint4*>(h);
    } else {
        size_t i = (size_t)(bid - DEC_BLOCKS) * 256 + threadIdx.x;   // 8-float group
        const float4* xp = reinterpret_cast<const float4*>(x) + i * 2;
        float4 v0 = xp[0];
        float4 v1 = xp[1];
        __align__(16) __half h[8];
        h[0] = __float2half_rn(v0.x); h[1] = __float2half_rn(v0.y);
        h[2] = __float2half_rn(v0.z); h[3] = __float2half_rn(v0.w);
        h[4] = __float2half_rn(v1.x); h[5] = __float2half_rn(v1.y);
        h[6] = __float2half_rn(v1.z); h[7] = __float2half_rn(v1.w);
        *reinterpret_cast<uint4*>(&g_xf[i * 8]) = *reinterpret_cast<uint4*>(h);
    }
}

// ---------------------------------------------------------------------------
// Single-pass fp16 GEMM (fp32 accum): C = xf @ Wf^T + bias
// PERSISTENT: 148 CTAs, each loops over ~7 output tiles (tile += 148).
// Per tile: 128x256, BK=128, 2-stage cp.async, one barrier per chunk,
// 16 warps of 64x32. Next-chunk loads (wrapping to the next tile's chunk 0)
// trickled in 4 parts after k-steps 0..3.
// ---------------------------------------------------------------------------
__global__ void __launch_bounds__(NTHREADS, 1) gemm_mma_kernel(
    const float* __restrict__ bias,
    float* __restrict__ C)
{
    extern __shared__ char smem[];
    const uint32_t sb = smem_u32(smem);
    const int tid  = threadIdx.x;
    const int wid  = tid >> 5;
    const int lane = tid & 31;
    const int warp_m = (wid >> 3) * 64;     // 0 or 64
    const int warp_n = (wid & 7) * 32;      // 0,32,...,224

    // One quarter of a chunk's loads: part p covers A seg p and B segs 2p,2p+1.
    auto issue_part = [&](int lbm, int lbn, int k0, int stg, int p) {
        const uint32_t sbase = sb + (uint32_t)stg * STAGEB;
        {
            const int u = tid + p * NTHREADS;
            const int r = u >> 4;              // 0..127
            const int c = u & 15;              // 16B segment
            const uint32_t so = (uint32_t)(r * PITCHB + c * 16);
            cp16(sbase + SA_OFF + so, g_xf + (size_t)(lbm + r) * IN_DIM + k0 + c * 8);
        }
        #pragma unroll
        for (int i = 0; i < 2; i++) {
            const int u = tid + (p * 2 + i) * NTHREADS;
            const int r = u >> 4;              // 0..255
            const int c = u & 15;
            const uint32_t so = (uint32_t)(r * PITCHB + c * 16);
            cp16(sbase + SB_OFF + so, g_Wf + (size_t)(lbn + r) * IN_DIM + k0 + c * 8);
        }
    };

    // ldmatrix lane addressing (byte offsets within a tile)
    const uint32_t a_lane_off =
        (uint32_t)((warp_m + (lane & 15)) * PITCHB + (lane >> 4) * 16);
    const int b_n0 = warp_n + (lane & 7) + ((lane >> 4) << 3);
    const uint32_t b_lane_off =
        (uint32_t)(b_n0 * PITCHB + ((lane >> 3) & 1) * 16);

    const int erow = lane >> 2;
    const int ecol = (lane & 3) * 2;

    // Prologue: first tile's chunk 0 into stage 0.
    {
        const int t0 = blockIdx.x;
        const int pbm = (t0 >> 4) * BM;
        const int pbn = (t0 & 15) * BN;
        #pragma unroll
        for (int p = 0; p < 4; p++) issue_part(pbm, pbn, 0, 0, p);
        cp_commit();
    }

    int stg = 0;
    for (int tile = blockIdx.x; tile < NTILES; tile += NCTAS) {
        const int bm = (tile >> 4) * BM;
        const int bn = (tile & 15) * BN;

        float acc[4][4][4];
        #pragma unroll
        for (int m = 0; m < 4; m++)
            #pragma unroll
            for (int n = 0; n < 4; n++)
                #pragma unroll
                for (int v = 0; v < 4; v++) acc[m][n][v] = 0.0f;

        for (int ch = 0; ch < NCHUNK; ch++) {
            cp_wait0();
            __syncthreads();            // single barrier per chunk

            // coordinates of the chunk to load (next chunk, wrapping to next tile)
            int  nch  = ch + 1;
            int  ntile = tile;
            bool more = true;
            if (nch == NCHUNK) {
                nch = 0;
                ntile = tile + NCTAS;
                if (ntile >= NTILES) more = false;
            }
            const int nbm = (ntile >> 4) * BM;
            const int nbn = (ntile & 15) * BN;
            const int nk0 = nch * BK;
            const int nstg = stg ^ 1;

            const uint32_t sbase = sb + (uint32_t)stg * STAGEB;
            #pragma unroll
            for (int s16 = 0; s16 < 8; s16++) {
                const uint32_t kb = (uint32_t)(s16 * 32);   // 16 fp16 = 32B
                uint32_t ah[4][4];
                #pragma unroll
                for (int m = 0; m < 4; m++) {
                    const uint32_t off = a_lane_off + (uint32_t)(m * 16 * PITCHB) + kb;
                    ldm_x4(ah[m], sbase + SA_OFF + off);
                }
                #pragma unroll
                for (int np = 0; np < 2; np++) {            // 2 x 16-col B blocks
                    const uint32_t off = b_lane_off + (uint32_t)(np * 16 * PITCHB) + kb;
                    uint32_t th[4];
                    ldm_x4(th, sbase + SB_OFF + off);
                    #pragma unroll
                    for (int m = 0; m < 4; m++) {
                        mma16816(acc[m][np * 2],     ah[m], th);
                        mma16816(acc[m][np * 2 + 1], ah[m], th + 2);
                    }
                }
                // trickle next-chunk loads after k-steps 0..3; commit after last
                if (more && s16 < 4) {
                    issue_part(nbm, nbn, nk0, nstg, s16);
                    if (s16 == 3) cp_commit();
                }
            }
            stg ^= 1;
        }

        // Epilogue (overlaps the in-flight next-tile chunk-0 loads)
        #pragma unroll
        for (int m = 0; m < 4; m++) {
            const size_t row = (size_t)(bm + warp_m + m * 16 + erow);
            #pragma unroll
            for (int n = 0; n < 4; n++) {
                const int col = bn + warp_n + n * 8 + ecol;
                const float bx = bias[col], by = bias[col + 1];
                float2 o0 = make_float2(acc[m][n][0] + bx, acc[m][n][1] + by);
                float2 o1 = make_float2(acc[m][n][2] + bx, acc[m][n][3] + by);
                *reinterpret_cast<float2*>(C + row * OUT_DIM + col) = o0;
                *reinterpret_cast<float2*>(C + (row + 8) * OUT_DIM + col) = o1;
            }
        }
    }
}

// ---------------------------------------------------------------------------
// Launch
// ---------------------------------------------------------------------------
extern "C" void kernel_launch(void* const* d_in, const int* in_sizes, int n_in,
                              void* d_out, int out_size)
{
    const float* x         = (const float*)d_in[0];      // [4,2048,4096]
    const float* centroids = (const float*)d_in[1];      // [256,8]
    const int*   labels    = (const int*)d_in[2];        // [2097152] int32
    const float* scale     = (const float*)d_in[3];      // [4096]
    const float* bias      = (const float*)d_in[4];      // [4096]
    float*       out       = (float*)d_out;              // [8192,4096]

    (void)in_sizes; (void)n_in; (void)out_size;

    cudaFuncSetAttribute(gemm_mma_kernel,
                         cudaFuncAttributeMaxDynamicSharedMemorySize, SMEM_TOTAL);

    prep_kernel<<<PREP_BLOCKS, 256>>>(labels, centroids, scale, x);
    gemm_mma_kernel<<<NCTAS, NTHREADS, SMEM_TOTAL>>>(bias, out);
}